// round 13
// baseline (speedup 1.0000x reference)
#include <cuda_runtime.h>
#include <cuda_fp16.h>
#include <cstdint>

#define N_REAL 7225      // 85*85 patches
#define NP     7424      // padded: 58*128 = 29*256
#define D_REAL 2331      // 259*9
#define KCH    146       // k-chunks of 16 halves (32B)
#define LD     (KCH * 16)   // 2336 halves
#define NH     85

#define BMr 128          // style rows per CTA tile
#define BNr 256          // img rows per CTA tile
#define CPS 5            // chunks per full stage
#define NSTG 30          // stages per tile: 29 full (5) + 1 partial (1)
#define LASTQ 1          // 146 - 29*5
#define SLOTS 3
#define NTIL_X 29        // NP/BNr
#define NTIL 1682        // 29 * 58
#define GRIDC 148        // persistent CTAs (1 per SM)

// per-chunk layout inside a slot: Ah (4KB) then Bh (8KB)
#define CHUNK_B 12288
#define SLOT_B (CPS * CHUNK_B)           // 61440

// smem map
#define FULL_OFF  0                       // 3 mbarriers * 8B
#define EMPTY_OFF 32                      // 3 mbarriers * 8B
#define TILE_OFF  1024
#define SMEM_TOTAL (TILE_OFF + SLOTS * SLOT_B)   // 185344

// ---------------- scratch (static device globals; no allocation) ------------
__device__ __half g_Ah[(size_t)KCH * NP * 16];   // style hi
__device__ __half g_Bh[(size_t)KCH * NP * 16];   // img hi
__device__ float g_sninv[NP];
__device__ float g_sn2[NP];
__device__ float g_in2[NP];
__device__ unsigned long long g_best[NP];
__device__ double g_acc;
__device__ int g_done;

// ---------------- helpers ----------------------------------------------------
__device__ __forceinline__ uint32_t smem_u32(const void* p) {
    uint32_t a;
    asm("{ .reg .u64 t; cvta.to.shared.u64 t, %1; cvt.u32.u64 %0, t; }" : "=r"(a) : "l"(p));
    return a;
}
__device__ __forceinline__ unsigned int encf(float f) {
    unsigned int u = __float_as_uint(f);
    unsigned int mask = (unsigned int)(-(int)(u >> 31)) | 0x80000000u;
    return u ^ mask;
}
__device__ __forceinline__ void ldsm4(uint32_t* r, uint32_t addr) {
    asm volatile("ldmatrix.sync.aligned.m8n8.x4.shared.b16 {%0,%1,%2,%3}, [%4];"
                 : "=r"(r[0]), "=r"(r[1]), "=r"(r[2]), "=r"(r[3]) : "r"(addr));
}
__device__ __forceinline__ void mma16816(float* c, const uint32_t* a, const uint32_t* b) {
    asm volatile(
        "mma.sync.aligned.m16n8k16.row.col.f32.f16.f16.f32 "
        "{%0,%1,%2,%3}, {%4,%5,%6,%7}, {%8,%9}, {%0,%1,%2,%3};"
        : "+f"(c[0]), "+f"(c[1]), "+f"(c[2]), "+f"(c[3])
        : "r"(a[0]), "r"(a[1]), "r"(a[2]), "r"(a[3]), "r"(b[0]), "r"(b[1]));
}
__device__ __forceinline__ void mbar_init(uint32_t mbar, uint32_t count) {
    asm volatile("mbarrier.init.shared.b64 [%0], %1;" :: "r"(mbar), "r"(count) : "memory");
}
__device__ __forceinline__ void mbar_arrive(uint32_t mbar) {
    asm volatile("mbarrier.arrive.shared.b64 _, [%0];" :: "r"(mbar) : "memory");
}
__device__ __forceinline__ void mbar_expect_tx(uint32_t mbar, uint32_t bytes) {
    asm volatile("mbarrier.arrive.expect_tx.shared.b64 _, [%0], %1;"
                 :: "r"(mbar), "r"(bytes) : "memory");
}
__device__ __forceinline__ void mbar_wait(uint32_t mbar, uint32_t phase) {
    uint32_t done;
    asm volatile(
        "{\n\t.reg .pred p;\n\t"
        "mbarrier.try_wait.parity.acquire.cta.shared::cta.b64 p, [%1], %2;\n\t"
        "selp.b32 %0, 1, 0, p;\n\t}"
        : "=r"(done) : "r"(mbar), "r"(phase) : "memory");
    while (!done) {
        asm volatile(
            "{\n\t.reg .pred p;\n\t"
            "mbarrier.try_wait.parity.acquire.cta.shared::cta.b64 p, [%1], %2, 0x989680;\n\t"
            "selp.b32 %0, 1, 0, p;\n\t}"
            : "=r"(done) : "r"(mbar), "r"(phase) : "memory");
    }
}
__device__ __forceinline__ void bulkcp(uint32_t dst, const void* src, uint32_t bytes,
                                       uint32_t mbar) {
    asm volatile(
        "cp.async.bulk.shared::cluster.global.mbarrier::complete_tx::bytes [%0], [%1], %2, [%3];"
        :: "r"(dst), "l"(src), "r"(bytes), "r"(mbar) : "memory");
}
#define FENCE_PROXY() asm volatile("fence.proxy.async.shared::cta;" ::: "memory")

__device__ __forceinline__ float block_reduce_sum(float v) {
    __shared__ float sh[32];
    int lane = threadIdx.x & 31, w = threadIdx.x >> 5;
    #pragma unroll
    for (int o = 16; o; o >>= 1) v += __shfl_xor_sync(0xffffffffu, v, o);
    if (lane == 0) sh[w] = v;
    __syncthreads();
    if (w == 0) {
        v = (lane < (int)(blockDim.x >> 5)) ? sh[lane] : 0.f;
        #pragma unroll
        for (int o = 16; o; o >>= 1) v += __shfl_xor_sync(0xffffffffu, v, o);
    }
    return v;
}

// ---------------- pack (both inputs) + fused norms + init -------------------
__global__ void pack_all(const float* __restrict__ respS,
                         const float* __restrict__ mapS,
                         const float* __restrict__ respI,
                         const float* __restrict__ mapI) {
    __shared__ float red[8][4];
    int t = threadIdx.x;
    int isImg = blockIdx.y;
    const float* resp = isImg ? respI : respS;
    const float* map  = isImg ? mapI  : mapS;
    __half* hiDst = isImg ? g_Bh : g_Ah;

    int p = t & 3;
    int i = blockIdx.x * 4 + p;
    int ph = i / NH, pw = i - ph * NH;
    bool valid = (i < N_REAL);
    int par = (i >> 2) & 1;

    if (!isImg && t < 4) g_best[i] = 0ull;
    if (blockIdx.x == 0 && blockIdx.y == 0 && t == 0) { g_acc = 0.0; g_done = 0; }

    float ss = 0.f;
    for (int d = (t >> 2); d < LD; d += 64) {
        float v = 0.f;
        if (valid && d < D_REAL) {
            int c = d / 9, rem = d - c * 9;
            int py = rem / 3, px = rem - py * 3;
            int row = ph * 3 + py, col = pw * 3 + px;
            if (c < 256) {
                v = resp[((size_t)c * 256 + row) * 256 + col];
            } else {
                int m = c - 256;
                const float* mp = map + (size_t)m * 1024 * 1024 + (size_t)(row * 4) * 1024 + col * 4;
                float s = 0.f;
                #pragma unroll
                for (int u = 0; u < 4; u++)
                    #pragma unroll
                    for (int w = 0; w < 4; w++) s += mp[u * 1024 + w];
                v = s * (50.0f / 16.0f);
            }
        }
        int d15 = d & 15;
        size_t off = ((size_t)(d >> 4) * NP + i) * 16 +
                     ((((d15 >> 3) ^ par) << 3) | (d15 & 7));
        hiDst[off] = __float2half_rn(v);
        ss += v * v;
    }
    #pragma unroll
    for (int o = 4; o < 32; o <<= 1) ss += __shfl_xor_sync(0xffffffffu, ss, o);
    int lane = t & 31, w = t >> 5;
    if (lane < 4) red[w][lane] = ss;
    __syncthreads();
    if (t < 32) {
        int pp = t & 3, ww = t >> 2;
        float v2 = red[ww][pp];
        #pragma unroll
        for (int o = 4; o < 32; o <<= 1) v2 += __shfl_xor_sync(0xffffffffu, v2, o);
        if (t < 4) {
            int ii = blockIdx.x * 4 + pp;
            if (isImg) {
                g_in2[ii] = v2;
            } else {
                g_sninv[ii] = (ii < N_REAL) ? rsqrtf(v2) : 0.f;
                g_sn2[ii] = v2;
            }
        }
    }
}

// ---------------- persistent HMMA GEMM + fused argmax ------------------------
__device__ __forceinline__ void issue_stage(uint32_t sb, int gst, int bid) {
    int s = gst % SLOTS;
    int tmine = gst / NSTG;
    int st = gst - tmine * NSTG;
    int nq = (st == NSTG - 1) ? LASTQ : CPS;
    int tid = bid + tmine * GRIDC;
    int ty = tid / NTIL_X;
    int i0 = ty * BMr;
    int j0 = (tid - ty * NTIL_X) * BNr;
    uint32_t full = sb + FULL_OFF + s * 8;
    uint32_t stg = sb + TILE_OFF + s * SLOT_B;
    mbar_expect_tx(full, (uint32_t)(nq * CHUNK_B));
    for (int q = 0; q < nq; q++) {
        int c = st * CPS + q;
        bulkcp(stg + q * CHUNK_B,        g_Ah + ((size_t)c * NP + i0) * 16, 4096, full);
        bulkcp(stg + q * CHUNK_B + 4096, g_Bh + ((size_t)c * NP + j0) * 16, 8192, full);
    }
}

struct Frag {
    uint32_t a[4][4];
    uint32_t b[8][2];
};
__device__ __forceinline__ void load_frags(Frag& f, uint32_t cb,
                                           const uint32_t* offA, const uint32_t* offB) {
    #pragma unroll
    for (int mt = 0; mt < 4; mt++) ldsm4(f.a[mt], cb + offA[mt]);
    #pragma unroll
    for (int pt = 0; pt < 4; pt++) {
        uint32_t r[4];
        ldsm4(r, cb + 4096 + offB[pt]);
        f.b[2 * pt][0] = r[0]; f.b[2 * pt][1] = r[1];
        f.b[2 * pt + 1][0] = r[2]; f.b[2 * pt + 1][1] = r[3];
    }
}

template <int NQ>
__device__ __forceinline__ void process_stage(
    uint32_t sb, int& gst, int totalStages, int bid,
    Frag* frag, int& cur, int* fph, int* eph,
    const uint32_t* offA, const uint32_t* offB,
    float (*acc)[8][4], int t, int lane)
{
    int s = gst % SLOTS;
    uint32_t stg = sb + TILE_OFF + s * SLOT_B;
    #pragma unroll
    for (int q = 0; q < NQ; q++) {
        bool lastAll = (gst == totalStages - 1) && (q == NQ - 1);
        if (!lastAll) {
            if (q < NQ - 1) {
                load_frags(frag[cur ^ 1], stg + (q + 1) * CHUNK_B, offA, offB);
            } else {
                int ns = (gst + 1) % SLOTS;
                mbar_wait(sb + FULL_OFF + ns * 8, fph[ns]);
                fph[ns] ^= 1;
                load_frags(frag[cur ^ 1], sb + TILE_OFF + ns * SLOT_B, offA, offB);
            }
        }
        #pragma unroll
        for (int mt = 0; mt < 4; mt++)
            #pragma unroll
            for (int nt = 0; nt < 8; nt++)
                mma16816(acc[mt][nt], frag[cur].a[mt], frag[cur].b[nt]);
        if (q == NQ - 1) {
            // this warp is done reading slot s for this stage
            if (lane == 0) mbar_arrive(sb + EMPTY_OFF + s * 8);
            if (t == 0 && gst + SLOTS < totalStages) {
                mbar_wait(sb + EMPTY_OFF + s * 8, eph[s]);   // all 8 warps released slot
                FENCE_PROXY();
                issue_stage(sb, gst + SLOTS, bid);
            }
            eph[s] ^= 1;
        }
        cur ^= 1;
    }
    gst++;
}

__global__ void __launch_bounds__(256, 1)
gemm_hmma_persistent() {
    extern __shared__ char smem[];
    uint32_t sb = smem_u32(smem);
    int t = threadIdx.x, lane = t & 31, w = t >> 5;
    int bid = blockIdx.x;
    int nMine = (NTIL - bid + GRIDC - 1) / GRIDC;
    int totalStages = nMine * NSTG;

    if (t < SLOTS) {
        mbar_init(sb + FULL_OFF + t * 8, 1);
        mbar_init(sb + EMPTY_OFF + t * 8, 8);
    }
    __syncthreads();
    if (t == 0) {
        FENCE_PROXY();
        issue_stage(sb, 0, bid);
        issue_stage(sb, 1, bid);
        issue_stage(sb, 2, bid);
    }

    int m0 = (w >> 2) * 64;   // warp row offset (0/64)
    int n0 = (w & 3) * 64;    // warp col offset (0/64/128/192)

    uint32_t offA[4], offB[4];
    #pragma unroll
    for (int mt = 0; mt < 4; mt++) {
        int row = m0 + mt * 16 + (lane & 15);
        int seg = lane >> 4;
        offA[mt] = (uint32_t)(row * 32 + ((seg ^ ((row >> 2) & 1)) << 4));
    }
    #pragma unroll
    for (int pt = 0; pt < 4; pt++) {
        int rr = n0 + pt * 16 + ((lane >> 4) << 3) + (lane & 7);
        int seg = (lane >> 3) & 1;
        offB[pt] = (uint32_t)(rr * 32 + ((seg ^ ((rr >> 2) & 1)) << 4));
    }

    float acc[4][8][4];
    #pragma unroll
    for (int a = 0; a < 4; a++)
        #pragma unroll
        for (int b = 0; b < 8; b++)
            #pragma unroll
            for (int q = 0; q < 4; q++) acc[a][b][q] = 0.f;

    Frag frag[2];
    int fph[SLOTS] = {0, 0, 0};
    int eph[SLOTS] = {0, 0, 0};

    // prologue: wait slot 0, load its chunk-0 fragments
    mbar_wait(sb + FULL_OFF + 0, 0);
    fph[0] ^= 1;
    load_frags(frag[0], sb + TILE_OFF + 0, offA, offB);

    int cur = 0, gst = 0;
    for (int tt = 0; tt < nMine; tt++) {
        int tid = bid + tt * GRIDC;
        int ty = tid / NTIL_X;
        int i0 = ty * BMr;
        int j0 = (tid - ty * NTIL_X) * BNr;

        #pragma unroll 1
        for (int st = 0; st < NSTG - 1; st++)
            process_stage<CPS>(sb, gst, totalStages, bid, frag, cur, fph, eph,
                               offA, offB, acc, t, lane);
        process_stage<LASTQ>(sb, gst, totalStages, bid, frag, cur, fph, eph,
                             offA, offB, acc, t, lane);

        // ---- tile epilogue (warp-local): scale, argmax, atomicMax ----------
        int qlane = lane & 3;
        #pragma unroll
        for (int mt = 0; mt < 4; mt++) {
            #pragma unroll
            for (int h = 0; h < 2; h++) {
                unsigned long long key = 0ull;
                #pragma unroll
                for (int nt = 0; nt < 8; nt++) {
                    #pragma unroll
                    for (int e = 0; e < 2; e++) {
                        int jc = n0 + nt * 8 + 2 * qlane + e;
                        int j = j0 + jc;
                        float v = acc[mt][nt][2 * h + e] * __ldg(&g_sninv[j]);
                        if (j < N_REAL) {
                            unsigned long long k =
                                ((unsigned long long)encf(v) << 32) |
                                (unsigned long long)(0xFFFFFFFFu - (unsigned)j);
                            if (k > key) key = k;
                        }
                    }
                }
                #pragma unroll
                for (int o = 1; o < 4; o <<= 1) {
                    unsigned long long other = __shfl_xor_sync(0xffffffffu, key, o);
                    if (other > key) key = other;
                }
                int m = i0 + m0 + mt * 16 + h * 8 + (lane >> 2);
                if (qlane == 0 && m < N_REAL) atomicMax(&g_best[m], key);
                #pragma unroll
                for (int nt = 0; nt < 8; nt++) {
                    acc[mt][nt][2 * h + 0] = 0.f;
                    acc[mt][nt][2 * h + 1] = 0.f;
                }
            }
        }
    }
}

// ---------------- loss: gather dot + exact norms, last block finalizes ------
__global__ void loss_kernel(float* out) {
    int i = blockIdx.x;
    unsigned long long key = g_best[i];
    unsigned int n = 0xFFFFFFFFu - (unsigned int)(key & 0xFFFFFFFFull);
    int pi = (i >> 2) & 1, pn = ((int)n >> 2) & 1;
    float dot = 0.f;
    for (int g = threadIdx.x; g < LD / 8; g += blockDim.x) {
        int c = g >> 1, seg = g & 1;
        const __half2* ih = (const __half2*)(g_Bh + ((size_t)c * NP + i) * 16 +
                                             (size_t)((seg ^ pi) << 3));
        const __half2* sh2 = (const __half2*)(g_Ah + ((size_t)c * NP + n) * 16 +
                                              (size_t)((seg ^ pn) << 3));
        #pragma unroll
        for (int q = 0; q < 4; q++) {
            float2 a = __half22float2(ih[q]);
            float2 b = __half22float2(sh2[q]);
            dot += a.x * b.x + a.y * b.y;
        }
    }
    dot = block_reduce_sum(dot);
    if (threadIdx.x == 0) {
        float s = g_in2[i] + g_sn2[n] - 2.f * dot;
        atomicAdd(&g_acc, (double)s);
        __threadfence();
        int ticket = atomicAdd(&g_done, 1);
        if (ticket == N_REAL - 1)
            out[0] = (float)(g_acc / ((double)D_REAL * (double)N_REAL));
    }
}

// ---------------- launch ----------------------------------------------------
extern "C" void kernel_launch(void* const* d_in, const int* in_sizes, int n_in,
                              void* d_out, int out_size) {
    const float* bigs[2] = {nullptr, nullptr};
    const float* smalls[2] = {nullptr, nullptr};
    int bi = 0, si = 0;
    for (int k = 0; k < n_in; k++) {
        if (in_sizes[k] == 256 * 256 * 256) { if (bi < 2) bigs[bi++] = (const float*)d_in[k]; }
        else                                { if (si < 2) smalls[si++] = (const float*)d_in[k]; }
    }
    const float* style_resp = bigs[0];
    const float* model_resp = bigs[1];
    const float* style_map  = smalls[0];
    const float* output_map = smalls[1];

    cudaFuncSetAttribute(gemm_hmma_persistent,
                         cudaFuncAttributeMaxDynamicSharedMemorySize, SMEM_TOTAL);

    pack_all<<<dim3(NP / 4, 2), 256>>>(style_resp, style_map, model_resp, output_map);
    gemm_hmma_persistent<<<GRIDC, 256, SMEM_TOTAL>>>();
    loss_kernel<<<N_REAL, 256>>>((float*)d_out);
}

// round 15
// speedup vs baseline: 2.1896x; 2.1896x over previous
#include <cuda_runtime.h>
#include <cuda_fp16.h>
#include <cstdint>

#define N_REAL 7225      // 85*85 patches
#define NP     7424      // padded: 58*128 = 29*256
#define D_REAL 2331      // 259*9
#define KCH    146       // k-chunks of 16 halves (32B): 18 stages of 8 + 1 of 2
#define LD     (KCH * 16)   // 2336 halves
#define NH     85

#define BMr 128          // style rows per CTA tile
#define BNr 256          // img rows per CTA tile
#define CPS 8            // chunks per full stage
#define NST 19           // stages per tile (18 full + 1 partial)
#define LASTQ (KCH - (NST - 1) * CPS)   // 2
#define NTIL_X 29        // NP/BNr
#define NTIL 1682        // 29 * 58
#define GRIDC 148        // persistent CTAs (1 per SM)

// per-chunk layout inside a stage: Ah (4KB) then Bh (8KB)
#define CHUNK_B 12288
#define STAGE_B (CPS * CHUNK_B)          // 98304 (slot size; partial stage uses prefix)

// smem map
#define FULL_OFF 0                        // 2 mbarriers * 8B
#define TILE_OFF 1024
#define SMEM_TOTAL (TILE_OFF + 2 * STAGE_B)   // 197632

// ---------------- scratch (static device globals; no allocation) ------------
__device__ __half g_Ah[(size_t)KCH * NP * 16];   // style hi
__device__ __half g_Bh[(size_t)KCH * NP * 16];   // img hi
__device__ float g_sninv[NP];
__device__ float g_sn2[NP];
__device__ float g_in2[NP];
__device__ unsigned long long g_best[NP];
__device__ double g_acc;
__device__ int g_done;

// ---------------- helpers ----------------------------------------------------
__device__ __forceinline__ uint32_t smem_u32(const void* p) {
    uint32_t a;
    asm("{ .reg .u64 t; cvta.to.shared.u64 t, %1; cvt.u32.u64 %0, t; }" : "=r"(a) : "l"(p));
    return a;
}
__device__ __forceinline__ unsigned int encf(float f) {
    unsigned int u = __float_as_uint(f);
    unsigned int mask = (unsigned int)(-(int)(u >> 31)) | 0x80000000u;
    return u ^ mask;
}
__device__ __forceinline__ void ldsm4(uint32_t* r, uint32_t addr) {
    asm volatile("ldmatrix.sync.aligned.m8n8.x4.shared.b16 {%0,%1,%2,%3}, [%4];"
                 : "=r"(r[0]), "=r"(r[1]), "=r"(r[2]), "=r"(r[3]) : "r"(addr));
}
__device__ __forceinline__ void mma16816(float* c, const uint32_t* a, const uint32_t* b) {
    asm volatile(
        "mma.sync.aligned.m16n8k16.row.col.f32.f16.f16.f32 "
        "{%0,%1,%2,%3}, {%4,%5,%6,%7}, {%8,%9}, {%0,%1,%2,%3};"
        : "+f"(c[0]), "+f"(c[1]), "+f"(c[2]), "+f"(c[3])
        : "r"(a[0]), "r"(a[1]), "r"(a[2]), "r"(a[3]), "r"(b[0]), "r"(b[1]));
}
__device__ __forceinline__ void mbar_init(uint32_t mbar, uint32_t count) {
    asm volatile("mbarrier.init.shared.b64 [%0], %1;" :: "r"(mbar), "r"(count) : "memory");
}
__device__ __forceinline__ void mbar_expect_tx(uint32_t mbar, uint32_t bytes) {
    asm volatile("mbarrier.arrive.expect_tx.shared.b64 _, [%0], %1;"
                 :: "r"(mbar), "r"(bytes) : "memory");
}
__device__ __forceinline__ void mbar_wait(uint32_t mbar, uint32_t phase) {
    uint32_t done;
    asm volatile(
        "{\n\t.reg .pred p;\n\t"
        "mbarrier.try_wait.parity.acquire.cta.shared::cta.b64 p, [%1], %2;\n\t"
        "selp.b32 %0, 1, 0, p;\n\t}"
        : "=r"(done) : "r"(mbar), "r"(phase) : "memory");
    while (!done) {
        asm volatile(
            "{\n\t.reg .pred p;\n\t"
            "mbarrier.try_wait.parity.acquire.cta.shared::cta.b64 p, [%1], %2, 0x989680;\n\t"
            "selp.b32 %0, 1, 0, p;\n\t}"
            : "=r"(done) : "r"(mbar), "r"(phase) : "memory");
    }
}
__device__ __forceinline__ void bulkcp(uint32_t dst, const void* src, uint32_t bytes,
                                       uint32_t mbar) {
    asm volatile(
        "cp.async.bulk.shared::cluster.global.mbarrier::complete_tx::bytes [%0], [%1], %2, [%3];"
        :: "r"(dst), "l"(src), "r"(bytes), "r"(mbar) : "memory");
}
#define FENCE_PROXY() asm volatile("fence.proxy.async.shared::cta;" ::: "memory")

__device__ __forceinline__ float block_reduce_sum(float v) {
    __shared__ float sh[32];
    int lane = threadIdx.x & 31, w = threadIdx.x >> 5;
    #pragma unroll
    for (int o = 16; o; o >>= 1) v += __shfl_xor_sync(0xffffffffu, v, o);
    if (lane == 0) sh[w] = v;
    __syncthreads();
    if (w == 0) {
        v = (lane < (int)(blockDim.x >> 5)) ? sh[lane] : 0.f;
        #pragma unroll
        for (int o = 16; o; o >>= 1) v += __shfl_xor_sync(0xffffffffu, v, o);
    }
    return v;
}

// ---------------- pack (both inputs) + fused norms + init -------------------
__global__ void pack_all(const float* __restrict__ respS,
                         const float* __restrict__ mapS,
                         const float* __restrict__ respI,
                         const float* __restrict__ mapI) {
    __shared__ float red[8][4];
    int t = threadIdx.x;
    int isImg = blockIdx.y;
    const float* resp = isImg ? respI : respS;
    const float* map  = isImg ? mapI  : mapS;
    __half* hiDst = isImg ? g_Bh : g_Ah;

    int p = t & 3;
    int i = blockIdx.x * 4 + p;
    int ph = i / NH, pw = i - ph * NH;
    bool valid = (i < N_REAL);
    int par = (i >> 2) & 1;

    if (!isImg && t < 4) g_best[i] = 0ull;
    if (blockIdx.x == 0 && blockIdx.y == 0 && t == 0) { g_acc = 0.0; g_done = 0; }

    float ss = 0.f;
    for (int d = (t >> 2); d < LD; d += 64) {
        float v = 0.f;
        if (valid && d < D_REAL) {
            int c = d / 9, rem = d - c * 9;
            int py = rem / 3, px = rem - py * 3;
            int row = ph * 3 + py, col = pw * 3 + px;
            if (c < 256) {
                v = resp[((size_t)c * 256 + row) * 256 + col];
            } else {
                int m = c - 256;
                const float* mp = map + (size_t)m * 1024 * 1024 + (size_t)(row * 4) * 1024 + col * 4;
                float s = 0.f;
                #pragma unroll
                for (int u = 0; u < 4; u++)
                    #pragma unroll
                    for (int w = 0; w < 4; w++) s += mp[u * 1024 + w];
                v = s * (50.0f / 16.0f);
            }
        }
        int d15 = d & 15;
        size_t off = ((size_t)(d >> 4) * NP + i) * 16 +
                     ((((d15 >> 3) ^ par) << 3) | (d15 & 7));
        hiDst[off] = __float2half_rn(v);
        ss += v * v;
    }
    #pragma unroll
    for (int o = 4; o < 32; o <<= 1) ss += __shfl_xor_sync(0xffffffffu, ss, o);
    int lane = t & 31, w = t >> 5;
    if (lane < 4) red[w][lane] = ss;
    __syncthreads();
    if (t < 32) {
        int pp = t & 3, ww = t >> 2;
        float v2 = red[ww][pp];
        #pragma unroll
        for (int o = 4; o < 32; o <<= 1) v2 += __shfl_xor_sync(0xffffffffu, v2, o);
        if (t < 4) {
            int ii = blockIdx.x * 4 + pp;
            if (isImg) {
                g_in2[ii] = v2;
            } else {
                g_sninv[ii] = (ii < N_REAL) ? rsqrtf(v2) : 0.f;
                g_sn2[ii] = v2;
            }
        }
    }
}

// ---------------- persistent HMMA GEMM + fused argmax (Round-11 design) -----
__device__ __forceinline__ void issue_stage(uint32_t sb, int gst, int bid) {
    int s = gst & 1;
    int tmine = gst / NST;
    int st = gst - tmine * NST;
    int nq = (st == NST - 1) ? LASTQ : CPS;
    int tid = bid + tmine * GRIDC;
    int ty = tid / NTIL_X;
    int i0 = ty * BMr;
    int j0 = (tid - ty * NTIL_X) * BNr;
    uint32_t full = sb + FULL_OFF + s * 8;
    uint32_t stg = sb + TILE_OFF + s * STAGE_B;
    mbar_expect_tx(full, (uint32_t)(nq * CHUNK_B));
    for (int q = 0; q < nq; q++) {
        int c = st * CPS + q;
        bulkcp(stg + q * CHUNK_B,        g_Ah + ((size_t)c * NP + i0) * 16, 4096, full);
        bulkcp(stg + q * CHUNK_B + 4096, g_Bh + ((size_t)c * NP + j0) * 16, 8192, full);
    }
}

struct Frag {
    uint32_t a[4][4];
    uint32_t b[8][2];
};
__device__ __forceinline__ void load_frags(Frag& f, uint32_t cb,
                                           const uint32_t* offA, const uint32_t* offB) {
    #pragma unroll
    for (int mt = 0; mt < 4; mt++) ldsm4(f.a[mt], cb + offA[mt]);
    #pragma unroll
    for (int pt = 0; pt < 4; pt++) {
        uint32_t r[4];
        ldsm4(r, cb + 4096 + offB[pt]);
        f.b[2 * pt][0] = r[0]; f.b[2 * pt][1] = r[1];
        f.b[2 * pt + 1][0] = r[2]; f.b[2 * pt + 1][1] = r[3];
    }
}

template <int NQ>
__device__ __forceinline__ void process_stage(
    uint32_t sb, int& gst, int totalStages, int bid,
    Frag* frag, int& cur, int* phase,
    const uint32_t* offA, const uint32_t* offB,
    float (*acc)[8][4], int t)
{
    int s = gst & 1;
    uint32_t stg = sb + TILE_OFF + s * STAGE_B;
    #pragma unroll
    for (int q = 0; q < NQ; q++) {
        bool lastAll = (gst == totalStages - 1) && (q == NQ - 1);
        if (!lastAll) {
            if (q < NQ - 1) {
                load_frags(frag[cur ^ 1], stg + (q + 1) * CHUNK_B, offA, offB);
            } else {
                int ns = (gst + 1) & 1;
                mbar_wait(sb + FULL_OFF + ns * 8, phase[ns]);
                phase[ns] ^= 1;
                load_frags(frag[cur ^ 1], sb + TILE_OFF + ns * STAGE_B, offA, offB);
            }
        }
        if (q == NQ - 1) {
            __syncthreads();   // all warps done with ldsm from slot s
            if (t == 0 && gst + 2 < totalStages) {
                FENCE_PROXY();
                issue_stage(sb, gst + 2, bid);
            }
        }
        #pragma unroll
        for (int mt = 0; mt < 4; mt++)
            #pragma unroll
            for (int nt = 0; nt < 8; nt++)
                mma16816(acc[mt][nt], frag[cur].a[mt], frag[cur].b[nt]);
        cur ^= 1;
    }
    gst++;
}

__global__ void __launch_bounds__(256, 1)
gemm_hmma_persistent() {
    extern __shared__ char smem[];
    uint32_t sb = smem_u32(smem);
    int t = threadIdx.x, lane = t & 31, w = t >> 5;
    int bid = blockIdx.x;
    int nMine = (NTIL - bid + GRIDC - 1) / GRIDC;
    int totalStages = nMine * NST;

    if (t < 2) mbar_init(sb + FULL_OFF + t * 8, 1);
    __syncthreads();
    if (t == 0) {
        FENCE_PROXY();
        issue_stage(sb, 0, bid);
        issue_stage(sb, 1, bid);
    }

    int m0 = (w >> 2) * 64;   // warp row offset (0/64)
    int n0 = (w & 3) * 64;    // warp col offset (0/64/128/192)

    uint32_t offA[4], offB[4];
    #pragma unroll
    for (int mt = 0; mt < 4; mt++) {
        int row = m0 + mt * 16 + (lane & 15);
        int seg = lane >> 4;
        offA[mt] = (uint32_t)(row * 32 + ((seg ^ ((row >> 2) & 1)) << 4));
    }
    #pragma unroll
    for (int pt = 0; pt < 4; pt++) {
        int rr = n0 + pt * 16 + ((lane >> 4) << 3) + (lane & 7);
        int seg = (lane >> 3) & 1;
        offB[pt] = (uint32_t)(rr * 32 + ((seg ^ ((rr >> 2) & 1)) << 4));
    }

    float acc[4][8][4];
    #pragma unroll
    for (int a = 0; a < 4; a++)
        #pragma unroll
        for (int b = 0; b < 8; b++)
            #pragma unroll
            for (int q = 0; q < 4; q++) acc[a][b][q] = 0.f;

    Frag frag[2];
    int phase[2] = {0, 0};

    // prologue: wait stage 0, load its chunk-0 fragments
    mbar_wait(sb + FULL_OFF + 0, 0);
    phase[0] ^= 1;
    load_frags(frag[0], sb + TILE_OFF + 0, offA, offB);

    int cur = 0, gst = 0;
    for (int tt = 0; tt < nMine; tt++) {
        int tid = bid + tt * GRIDC;
        int ty = tid / NTIL_X;
        int i0 = ty * BMr;
        int j0 = (tid - ty * NTIL_X) * BNr;

        #pragma unroll 1
        for (int st = 0; st < NST - 1; st++)
            process_stage<CPS>(sb, gst, totalStages, bid, frag, cur, phase,
                               offA, offB, acc, t);
        process_stage<LASTQ>(sb, gst, totalStages, bid, frag, cur, phase,
                             offA, offB, acc, t);

        // ---- tile epilogue: scale by sninv[j], per-row argmax, atomicMax ----
        int qlane = lane & 3;
        #pragma unroll
        for (int mt = 0; mt < 4; mt++) {
            #pragma unroll
            for (int h = 0; h < 2; h++) {
                unsigned long long key = 0ull;
                #pragma unroll
                for (int nt = 0; nt < 8; nt++) {
                    #pragma unroll
                    for (int e = 0; e < 2; e++) {
                        int jc = n0 + nt * 8 + 2 * qlane + e;
                        int j = j0 + jc;
                        float v = acc[mt][nt][2 * h + e] * __ldg(&g_sninv[j]);
                        if (j < N_REAL) {
                            unsigned long long k =
                                ((unsigned long long)encf(v) << 32) |
                                (unsigned long long)(0xFFFFFFFFu - (unsigned)j);
                            if (k > key) key = k;
                        }
                    }
                }
                #pragma unroll
                for (int o = 1; o < 4; o <<= 1) {
                    unsigned long long other = __shfl_xor_sync(0xffffffffu, key, o);
                    if (other > key) key = other;
                }
                int m = i0 + m0 + mt * 16 + h * 8 + (lane >> 2);
                if (qlane == 0 && m < N_REAL) atomicMax(&g_best[m], key);
                #pragma unroll
                for (int nt = 0; nt < 8; nt++) {
                    acc[mt][nt][2 * h + 0] = 0.f;
                    acc[mt][nt][2 * h + 1] = 0.f;
                }
            }
        }
    }
}

// ---------------- loss: gather dot + exact norms, last block finalizes ------
__global__ void loss_kernel(float* out) {
    int i = blockIdx.x;
    unsigned long long key = g_best[i];
    unsigned int n = 0xFFFFFFFFu - (unsigned int)(key & 0xFFFFFFFFull);
    int pi = (i >> 2) & 1, pn = ((int)n >> 2) & 1;
    float dot = 0.f;
    for (int g = threadIdx.x; g < LD / 8; g += blockDim.x) {
        int c = g >> 1, seg = g & 1;
        const __half2* ih = (const __half2*)(g_Bh + ((size_t)c * NP + i) * 16 +
                                             (size_t)((seg ^ pi) << 3));
        const __half2* sh2 = (const __half2*)(g_Ah + ((size_t)c * NP + n) * 16 +
                                              (size_t)((seg ^ pn) << 3));
        #pragma unroll
        for (int q = 0; q < 4; q++) {
            float2 a = __half22float2(ih[q]);
            float2 b = __half22float2(sh2[q]);
            dot += a.x * b.x + a.y * b.y;
        }
    }
    dot = block_reduce_sum(dot);
    if (threadIdx.x == 0) {
        float s = g_in2[i] + g_sn2[n] - 2.f * dot;
        atomicAdd(&g_acc, (double)s);
        __threadfence();
        int ticket = atomicAdd(&g_done, 1);
        if (ticket == N_REAL - 1)
            out[0] = (float)(g_acc / ((double)D_REAL * (double)N_REAL));
    }
}

// ---------------- launch ----------------------------------------------------
extern "C" void kernel_launch(void* const* d_in, const int* in_sizes, int n_in,
                              void* d_out, int out_size) {
    const float* bigs[2] = {nullptr, nullptr};
    const float* smalls[2] = {nullptr, nullptr};
    int bi = 0, si = 0;
    for (int k = 0; k < n_in; k++) {
        if (in_sizes[k] == 256 * 256 * 256) { if (bi < 2) bigs[bi++] = (const float*)d_in[k]; }
        else                                { if (si < 2) smalls[si++] = (const float*)d_in[k]; }
    }
    const float* style_resp = bigs[0];
    const float* model_resp = bigs[1];
    const float* style_map  = smalls[0];
    const float* output_map = smalls[1];

    cudaFuncSetAttribute(gemm_hmma_persistent,
                         cudaFuncAttributeMaxDynamicSharedMemorySize, SMEM_TOTAL);

    pack_all<<<dim3(NP / 4, 2), 256>>>(style_resp, style_map, model_resp, output_map);
    gemm_hmma_persistent<<<GRIDC, 256, SMEM_TOTAL>>>();
    loss_kernel<<<N_REAL, 256>>>((float*)d_out);
}

// round 16
// speedup vs baseline: 2.2341x; 1.0203x over previous
#include <cuda_runtime.h>
#include <cuda_fp16.h>
#include <cstdint>

#define N_REAL 7225      // 85*85 patches
#define NP     7424      // padded: 58*128
#define D_REAL 2331      // 259*9
#define KCH    146       // k-chunks of 16 halves (32B)
#define LD     (KCH * 16)   // 2336 halves
#define NH     85

#define BMr 128          // style rows per CTA tile
#define BNr 128          // img rows per CTA tile
#define CPS 5            // chunks per full stage
#define NST 30           // stages per tile (29 full + 1 of 1)
#define LASTQ (KCH - (NST - 1) * CPS)   // 1
#define NTIL_X 58        // NP/BNr
#define NTIL (58 * 58)   // 3364
#define GRIDC 296        // persistent CTAs (2 per SM)

// per-chunk layout inside a stage: Ah (4KB) then Bh (4KB)
#define CHUNK_B 8192
#define STAGE_B (CPS * CHUNK_B)          // 40960

// smem map
#define FULL_OFF 0                        // 2 mbarriers * 8B
#define TILE_OFF 1024
#define SMEM_TOTAL (TILE_OFF + 2 * STAGE_B)   // 82944 per CTA -> 2 CTAs/SM fit

// ---------------- scratch (static device globals; no allocation) ------------
__device__ __half g_Ah[(size_t)KCH * NP * 16];   // style hi
__device__ __half g_Bh[(size_t)KCH * NP * 16];   // img hi
__device__ float g_sninv[NP];
__device__ float g_sn2[NP];
__device__ float g_in2[NP];
__device__ unsigned long long g_best[NP];
__device__ double g_acc;
__device__ int g_done;

// ---------------- helpers ----------------------------------------------------
__device__ __forceinline__ uint32_t smem_u32(const void* p) {
    uint32_t a;
    asm("{ .reg .u64 t; cvta.to.shared.u64 t, %1; cvt.u32.u64 %0, t; }" : "=r"(a) : "l"(p));
    return a;
}
__device__ __forceinline__ unsigned int encf(float f) {
    unsigned int u = __float_as_uint(f);
    unsigned int mask = (unsigned int)(-(int)(u >> 31)) | 0x80000000u;
    return u ^ mask;
}
__device__ __forceinline__ void ldsm4(uint32_t* r, uint32_t addr) {
    asm volatile("ldmatrix.sync.aligned.m8n8.x4.shared.b16 {%0,%1,%2,%3}, [%4];"
                 : "=r"(r[0]), "=r"(r[1]), "=r"(r[2]), "=r"(r[3]) : "r"(addr));
}
__device__ __forceinline__ void mma16816(float* c, const uint32_t* a, const uint32_t* b) {
    asm volatile(
        "mma.sync.aligned.m16n8k16.row.col.f32.f16.f16.f32 "
        "{%0,%1,%2,%3}, {%4,%5,%6,%7}, {%8,%9}, {%0,%1,%2,%3};"
        : "+f"(c[0]), "+f"(c[1]), "+f"(c[2]), "+f"(c[3])
        : "r"(a[0]), "r"(a[1]), "r"(a[2]), "r"(a[3]), "r"(b[0]), "r"(b[1]));
}
__device__ __forceinline__ void mbar_init(uint32_t mbar, uint32_t count) {
    asm volatile("mbarrier.init.shared.b64 [%0], %1;" :: "r"(mbar), "r"(count) : "memory");
}
__device__ __forceinline__ void mbar_expect_tx(uint32_t mbar, uint32_t bytes) {
    asm volatile("mbarrier.arrive.expect_tx.shared.b64 _, [%0], %1;"
                 :: "r"(mbar), "r"(bytes) : "memory");
}
__device__ __forceinline__ void mbar_wait(uint32_t mbar, uint32_t phase) {
    uint32_t done;
    asm volatile(
        "{\n\t.reg .pred p;\n\t"
        "mbarrier.try_wait.parity.acquire.cta.shared::cta.b64 p, [%1], %2;\n\t"
        "selp.b32 %0, 1, 0, p;\n\t}"
        : "=r"(done) : "r"(mbar), "r"(phase) : "memory");
    while (!done) {
        asm volatile(
            "{\n\t.reg .pred p;\n\t"
            "mbarrier.try_wait.parity.acquire.cta.shared::cta.b64 p, [%1], %2, 0x989680;\n\t"
            "selp.b32 %0, 1, 0, p;\n\t}"
            : "=r"(done) : "r"(mbar), "r"(phase) : "memory");
    }
}
__device__ __forceinline__ void bulkcp(uint32_t dst, const void* src, uint32_t bytes,
                                       uint32_t mbar) {
    asm volatile(
        "cp.async.bulk.shared::cluster.global.mbarrier::complete_tx::bytes [%0], [%1], %2, [%3];"
        :: "r"(dst), "l"(src), "r"(bytes), "r"(mbar) : "memory");
}
#define FENCE_PROXY() asm volatile("fence.proxy.async.shared::cta;" ::: "memory")

__device__ __forceinline__ float block_reduce_sum(float v) {
    __shared__ float sh[32];
    int lane = threadIdx.x & 31, w = threadIdx.x >> 5;
    #pragma unroll
    for (int o = 16; o; o >>= 1) v += __shfl_xor_sync(0xffffffffu, v, o);
    if (lane == 0) sh[w] = v;
    __syncthreads();
    if (w == 0) {
        v = (lane < (int)(blockDim.x >> 5)) ? sh[lane] : 0.f;
        #pragma unroll
        for (int o = 16; o; o >>= 1) v += __shfl_xor_sync(0xffffffffu, v, o);
    }
    return v;
}

// ---------------- pack (both inputs) + fused norms + init -------------------
__global__ void pack_all(const float* __restrict__ respS,
                         const float* __restrict__ mapS,
                         const float* __restrict__ respI,
                         const float* __restrict__ mapI) {
    __shared__ float red[8][4];
    int t = threadIdx.x;
    int isImg = blockIdx.y;
    const float* resp = isImg ? respI : respS;
    const float* map  = isImg ? mapI  : mapS;
    __half* hiDst = isImg ? g_Bh : g_Ah;

    int p = t & 3;
    int i = blockIdx.x * 4 + p;
    int ph = i / NH, pw = i - ph * NH;
    bool valid = (i < N_REAL);
    int par = (i >> 2) & 1;

    if (!isImg && t < 4) g_best[i] = 0ull;
    if (blockIdx.x == 0 && blockIdx.y == 0 && t == 0) { g_acc = 0.0; g_done = 0; }

    int d = t >> 2;
    int c = d / 9;
    int rem = d - c * 9;
    int row0 = ph * 3, col0 = pw * 3;
    float ss = 0.f;
    for (; d < LD; d += 64) {
        float v = 0.f;
        if (valid && d < D_REAL) {
            int py = rem / 3, px = rem - py * 3;
            int row = row0 + py, col = col0 + px;
            if (c < 256) {
                v = resp[((uint32_t)c << 16) + ((uint32_t)row << 8) + (uint32_t)col];
            } else {
                int m = c - 256;
                const float* mp = map + (size_t)m * 1024 * 1024 + (size_t)(row * 4) * 1024 + col * 4;
                float s = 0.f;
                #pragma unroll
                for (int u = 0; u < 4; u++)
                    #pragma unroll
                    for (int w = 0; w < 4; w++) s += mp[u * 1024 + w];
                v = s * (50.0f / 16.0f);
            }
        }
        int d15 = d & 15;
        uint32_t off = ((uint32_t)(d >> 4) * (uint32_t)NP + (uint32_t)i) * 16u +
                       (uint32_t)((((d15 >> 3) ^ par) << 3) | (d15 & 7));
        hiDst[off] = __float2half_rn(v);
        ss += v * v;
        c += 7; rem += 1;
        if (rem >= 9) { rem -= 9; c += 1; }
    }
    #pragma unroll
    for (int o = 4; o < 32; o <<= 1) ss += __shfl_xor_sync(0xffffffffu, ss, o);
    int lane = t & 31, w = t >> 5;
    if (lane < 4) red[w][lane] = ss;
    __syncthreads();
    if (t < 32) {
        int pp = t & 3, ww = t >> 2;
        float v2 = red[ww][pp];
        #pragma unroll
        for (int o = 4; o < 32; o <<= 1) v2 += __shfl_xor_sync(0xffffffffu, v2, o);
        if (t < 4) {
            int ii = blockIdx.x * 4 + pp;
            if (isImg) {
                g_in2[ii] = v2;
            } else {
                g_sninv[ii] = (ii < N_REAL) ? rsqrtf(v2) : 0.f;
                g_sn2[ii] = v2;
            }
        }
    }
}

// ---------------- persistent HMMA GEMM, 2 CTA/SM, 128x128 tiles -------------
__device__ __forceinline__ void issue_stage(uint32_t sb, int gst, int bid) {
    int s = gst & 1;
    int tmine = gst / NST;
    int st = gst - tmine * NST;
    int nq = (st == NST - 1) ? LASTQ : CPS;
    int tid = bid + tmine * GRIDC;
    int ty = tid / NTIL_X;
    int i0 = ty * BMr;
    int j0 = (tid - ty * NTIL_X) * BNr;
    uint32_t full = sb + FULL_OFF + s * 8;
    uint32_t stg = sb + TILE_OFF + s * STAGE_B;
    mbar_expect_tx(full, (uint32_t)(nq * CHUNK_B));
    for (int q = 0; q < nq; q++) {
        int cc = st * CPS + q;
        bulkcp(stg + q * CHUNK_B,        g_Ah + ((size_t)cc * NP + i0) * 16, 4096, full);
        bulkcp(stg + q * CHUNK_B + 4096, g_Bh + ((size_t)cc * NP + j0) * 16, 4096, full);
    }
}

struct Frag {
    uint32_t a[2][4];
    uint32_t b[8][2];
};
__device__ __forceinline__ void load_frags(Frag& f, uint32_t cb,
                                           const uint32_t* offA, const uint32_t* offB) {
    #pragma unroll
    for (int mt = 0; mt < 2; mt++) ldsm4(f.a[mt], cb + offA[mt]);
    #pragma unroll
    for (int pt = 0; pt < 4; pt++) {
        uint32_t r[4];
        ldsm4(r, cb + 4096 + offB[pt]);
        f.b[2 * pt][0] = r[0]; f.b[2 * pt][1] = r[1];
        f.b[2 * pt + 1][0] = r[2]; f.b[2 * pt + 1][1] = r[3];
    }
}

template <int NQ>
__device__ __forceinline__ void process_stage(
    uint32_t sb, int& gst, int totalStages, int bid,
    int* phase, const uint32_t* offA, const uint32_t* offB,
    float (*acc)[8][4], int t)
{
    int s = gst & 1;
    uint32_t stg = sb + TILE_OFF + s * STAGE_B;
    mbar_wait(sb + FULL_OFF + s * 8, phase[s]);
    phase[s] ^= 1;
    #pragma unroll
    for (int q = 0; q < NQ; q++) {
        Frag f;
        load_frags(f, stg + q * CHUNK_B, offA, offB);
        #pragma unroll
        for (int mt = 0; mt < 2; mt++)
            #pragma unroll
            for (int nt = 0; nt < 8; nt++)
                mma16816(acc[mt][nt], f.a[mt], f.b[nt]);
    }
    __syncthreads();   // all warps done reading slot s
    if (t == 0 && gst + 2 < totalStages) {
        FENCE_PROXY();
        issue_stage(sb, gst + 2, bid);
    }
    gst++;
}

__global__ void __launch_bounds__(256, 2)
gemm_hmma_persistent() {
    extern __shared__ char smem[];
    uint32_t sb = smem_u32(smem);
    int t = threadIdx.x, lane = t & 31, w = t >> 5;
    int bid = blockIdx.x;
    int nMine = (NTIL - bid + GRIDC - 1) / GRIDC;
    if (nMine <= 0) return;
    int totalStages = nMine * NST;

    if (t < 2) mbar_init(sb + FULL_OFF + t * 8, 1);
    __syncthreads();
    if (t == 0) {
        FENCE_PROXY();
        issue_stage(sb, 0, bid);
        issue_stage(sb, 1, bid);
    }

    int m0 = (w >> 1) * 32;   // warp row offset (0/32/64/96)
    int n0 = (w & 1) * 64;    // warp col offset (0/64)

    uint32_t offA[2], offB[4];
    #pragma unroll
    for (int mt = 0; mt < 2; mt++) {
        int row = m0 + mt * 16 + (lane & 15);
        int seg = lane >> 4;
        offA[mt] = (uint32_t)(row * 32 + ((seg ^ ((row >> 2) & 1)) << 4));
    }
    #pragma unroll
    for (int pt = 0; pt < 4; pt++) {
        int rr = n0 + pt * 16 + ((lane >> 4) << 3) + (lane & 7);
        int seg = (lane >> 3) & 1;
        offB[pt] = (uint32_t)(rr * 32 + ((seg ^ ((rr >> 2) & 1)) << 4));
    }

    float acc[2][8][4];
    #pragma unroll
    for (int a = 0; a < 2; a++)
        #pragma unroll
        for (int b = 0; b < 8; b++)
            #pragma unroll
            for (int q = 0; q < 4; q++) acc[a][b][q] = 0.f;

    int phase[2] = {0, 0};
    int gst = 0;
    for (int tt = 0; tt < nMine; tt++) {
        int tid = bid + tt * GRIDC;
        int ty = tid / NTIL_X;
        int i0 = ty * BMr;
        int j0 = (tid - ty * NTIL_X) * BNr;

        #pragma unroll 1
        for (int st = 0; st < NST - 1; st++)
            process_stage<CPS>(sb, gst, totalStages, bid, phase, offA, offB, acc, t);
        process_stage<LASTQ>(sb, gst, totalStages, bid, phase, offA, offB, acc, t);

        // ---- tile epilogue: scale by sninv[j], per-row argmax, atomicMax ----
        int qlane = lane & 3;
        #pragma unroll
        for (int mt = 0; mt < 2; mt++) {
            #pragma unroll
            for (int h = 0; h < 2; h++) {
                unsigned long long key = 0ull;
                #pragma unroll
                for (int nt = 0; nt < 8; nt++) {
                    #pragma unroll
                    for (int e = 0; e < 2; e++) {
                        int jc = n0 + nt * 8 + 2 * qlane + e;
                        int j = j0 + jc;
                        float v = acc[mt][nt][2 * h + e] * __ldg(&g_sninv[j]);
                        if (j < N_REAL) {
                            unsigned long long k =
                                ((unsigned long long)encf(v) << 32) |
                                (unsigned long long)(0xFFFFFFFFu - (unsigned)j);
                            if (k > key) key = k;
                        }
                    }
                }
                #pragma unroll
                for (int o = 1; o < 4; o <<= 1) {
                    unsigned long long other = __shfl_xor_sync(0xffffffffu, key, o);
                    if (other > key) key = other;
                }
                int m = i0 + m0 + mt * 16 + h * 8 + (lane >> 2);
                if (qlane == 0 && m < N_REAL) atomicMax(&g_best[m], key);
                #pragma unroll
                for (int nt = 0; nt < 8; nt++) {
                    acc[mt][nt][2 * h + 0] = 0.f;
                    acc[mt][nt][2 * h + 1] = 0.f;
                }
            }
        }
    }
}

// ---------------- loss: gather dot + exact norms, last block finalizes ------
__global__ void loss_kernel(float* out) {
    int i = blockIdx.x;
    unsigned long long key = g_best[i];
    unsigned int n = 0xFFFFFFFFu - (unsigned int)(key & 0xFFFFFFFFull);
    int pi = (i >> 2) & 1, pn = ((int)n >> 2) & 1;
    float dot = 0.f;
    for (int g = threadIdx.x; g < LD / 8; g += blockDim.x) {
        int c = g >> 1, seg = g & 1;
        const __half2* ih = (const __half2*)(g_Bh + ((size_t)c * NP + i) * 16 +
                                             (size_t)((seg ^ pi) << 3));
        const __half2* sh2 = (const __half2*)(g_Ah + ((size_t)c * NP + n) * 16 +
                                              (size_t)((seg ^ pn) << 3));
        #pragma unroll
        for (int q = 0; q < 4; q++) {
            float2 a = __half22float2(ih[q]);
            float2 b = __half22float2(sh2[q]);
            dot += a.x * b.x + a.y * b.y;
        }
    }
    dot = block_reduce_sum(dot);
    if (threadIdx.x == 0) {
        float s = g_in2[i] + g_sn2[n] - 2.f * dot;
        atomicAdd(&g_acc, (double)s);
        __threadfence();
        int ticket = atomicAdd(&g_done, 1);
        if (ticket == N_REAL - 1)
            out[0] = (float)(g_acc / ((double)D_REAL * (double)N_REAL));
    }
}

// ---------------- launch ----------------------------------------------------
extern "C" void kernel_launch(void* const* d_in, const int* in_sizes, int n_in,
                              void* d_out, int out_size) {
    const float* bigs[2] = {nullptr, nullptr};
    const float* smalls[2] = {nullptr, nullptr};
    int bi = 0, si = 0;
    for (int k = 0; k < n_in; k++) {
        if (in_sizes[k] == 256 * 256 * 256) { if (bi < 2) bigs[bi++] = (const float*)d_in[k]; }
        else                                { if (si < 2) smalls[si++] = (const float*)d_in[k]; }
    }
    const float* style_resp = bigs[0];
    const float* model_resp = bigs[1];
    const float* style_map  = smalls[0];
    const float* output_map = smalls[1];

    cudaFuncSetAttribute(gemm_hmma_persistent,
                         cudaFuncAttributeMaxDynamicSharedMemorySize, SMEM_TOTAL);

    pack_all<<<dim3(NP / 4, 2), 256>>>(style_resp, style_map, model_resp, output_map);
    gemm_hmma_persistent<<<GRIDC, 256, SMEM_TOTAL>>>();
    loss_kernel<<<N_REAL, 256>>>((float*)d_out);
}

// round 17
// speedup vs baseline: 2.2649x; 1.0138x over previous
#include <cuda_runtime.h>
#include <cuda_fp16.h>
#include <cstdint>

#define N_REAL 7225      // 85*85 patches
#define NP     7424      // padded: 58*128
#define D_REAL 2331      // 259*9
#define KCH    146       // k-chunks of 16 halves (32B)
#define LD     (KCH * 16)   // 2336 halves
#define NH     85

#define BMr 128          // style rows per CTA tile
#define BNr 128          // img rows per CTA tile
#define CPS 6            // chunks per full stage
#define NST 25           // stages per tile (24 full + 1 of 2)
#define LASTQ (KCH - (NST - 1) * CPS)   // 2
#define NTIL_X 58        // NP/BNr
#define NTIL (58 * 58)   // 3364
#define GRIDC 296        // persistent CTAs (2 per SM)

// per-chunk layout inside a stage: Ah (4KB) then Bh (4KB)
#define CHUNK_B 8192
#define STAGE_B (CPS * CHUNK_B)          // 49152

// smem map
#define FULL_OFF 0                        // 2 mbarriers * 8B
#define TILE_OFF 1024
#define SMEM_TOTAL (TILE_OFF + 2 * STAGE_B)   // 99328 per CTA -> 2 CTAs/SM fit

// ---------------- scratch (static device globals; no allocation) ------------
__device__ __half g_Ah[(size_t)KCH * NP * 16];   // style hi
__device__ __half g_Bh[(size_t)KCH * NP * 16];   // img hi
__device__ float g_sninv[NP];
__device__ float g_sn2[NP];
__device__ float g_in2[NP];
__device__ unsigned long long g_best[NP];
__device__ double g_acc;
__device__ int g_done;

// ---------------- helpers ----------------------------------------------------
__device__ __forceinline__ uint32_t smem_u32(const void* p) {
    uint32_t a;
    asm("{ .reg .u64 t; cvta.to.shared.u64 t, %1; cvt.u32.u64 %0, t; }" : "=r"(a) : "l"(p));
    return a;
}
__device__ __forceinline__ unsigned int encf(float f) {
    unsigned int u = __float_as_uint(f);
    unsigned int mask = (unsigned int)(-(int)(u >> 31)) | 0x80000000u;
    return u ^ mask;
}
__device__ __forceinline__ void ldsm4(uint32_t* r, uint32_t addr) {
    asm volatile("ldmatrix.sync.aligned.m8n8.x4.shared.b16 {%0,%1,%2,%3}, [%4];"
                 : "=r"(r[0]), "=r"(r[1]), "=r"(r[2]), "=r"(r[3]) : "r"(addr));
}
__device__ __forceinline__ void mma16816(float* c, const uint32_t* a, const uint32_t* b) {
    asm volatile(
        "mma.sync.aligned.m16n8k16.row.col.f32.f16.f16.f32 "
        "{%0,%1,%2,%3}, {%4,%5,%6,%7}, {%8,%9}, {%0,%1,%2,%3};"
        : "+f"(c[0]), "+f"(c[1]), "+f"(c[2]), "+f"(c[3])
        : "r"(a[0]), "r"(a[1]), "r"(a[2]), "r"(a[3]), "r"(b[0]), "r"(b[1]));
}
__device__ __forceinline__ void mbar_init(uint32_t mbar, uint32_t count) {
    asm volatile("mbarrier.init.shared.b64 [%0], %1;" :: "r"(mbar), "r"(count) : "memory");
}
__device__ __forceinline__ void mbar_expect_tx(uint32_t mbar, uint32_t bytes) {
    asm volatile("mbarrier.arrive.expect_tx.shared.b64 _, [%0], %1;"
                 :: "r"(mbar), "r"(bytes) : "memory");
}
__device__ __forceinline__ void mbar_wait(uint32_t mbar, uint32_t phase) {
    uint32_t done;
    asm volatile(
        "{\n\t.reg .pred p;\n\t"
        "mbarrier.try_wait.parity.acquire.cta.shared::cta.b64 p, [%1], %2;\n\t"
        "selp.b32 %0, 1, 0, p;\n\t}"
        : "=r"(done) : "r"(mbar), "r"(phase) : "memory");
    while (!done) {
        asm volatile(
            "{\n\t.reg .pred p;\n\t"
            "mbarrier.try_wait.parity.acquire.cta.shared::cta.b64 p, [%1], %2, 0x989680;\n\t"
            "selp.b32 %0, 1, 0, p;\n\t}"
            : "=r"(done) : "r"(mbar), "r"(phase) : "memory");
    }
}
__device__ __forceinline__ void bulkcp(uint32_t dst, const void* src, uint32_t bytes,
                                       uint32_t mbar) {
    asm volatile(
        "cp.async.bulk.shared::cluster.global.mbarrier::complete_tx::bytes [%0], [%1], %2, [%3];"
        :: "r"(dst), "l"(src), "r"(bytes), "r"(mbar) : "memory");
}
#define FENCE_PROXY() asm volatile("fence.proxy.async.shared::cta;" ::: "memory")

__device__ __forceinline__ float block_reduce_sum(float v) {
    __shared__ float sh[32];
    int lane = threadIdx.x & 31, w = threadIdx.x >> 5;
    #pragma unroll
    for (int o = 16; o; o >>= 1) v += __shfl_xor_sync(0xffffffffu, v, o);
    if (lane == 0) sh[w] = v;
    __syncthreads();
    if (w == 0) {
        v = (lane < (int)(blockDim.x >> 5)) ? sh[lane] : 0.f;
        #pragma unroll
        for (int o = 16; o; o >>= 1) v += __shfl_xor_sync(0xffffffffu, v, o);
    }
    return v;
}

// ---------------- pack (both inputs) + fused norms + init -------------------
__global__ void pack_all(const float* __restrict__ respS,
                         const float* __restrict__ mapS,
                         const float* __restrict__ respI,
                         const float* __restrict__ mapI) {
    __shared__ float red[8][4];
    int t = threadIdx.x;
    int isImg = blockIdx.y;
    const float* resp = isImg ? respI : respS;
    const float* map  = isImg ? mapI  : mapS;
    __half* hiDst = isImg ? g_Bh : g_Ah;

    int p = t & 3;
    int i = blockIdx.x * 4 + p;
    int ph = i / NH, pw = i - ph * NH;
    bool valid = (i < N_REAL);
    int par = (i >> 2) & 1;

    if (!isImg && t < 4) g_best[i] = 0ull;
    if (blockIdx.x == 0 && blockIdx.y == 0 && t == 0) { g_acc = 0.0; g_done = 0; }

    int d0 = t >> 2;
    int c = d0 / 9;
    int rem = d0 - c * 9;
    int row0 = ph * 3, col0 = pw * 3;
    // loop-invariant swizzled position within the 16-half row; off is incremental
    int d15 = d0 & 15;
    uint32_t pos = (uint32_t)((((d15 >> 3) ^ par) << 3) | (d15 & 7));
    uint32_t off = ((uint32_t)(d0 >> 4) * (uint32_t)NP + (uint32_t)i) * 16u + pos;
    const uint32_t OFF_STEP = 4u * (uint32_t)NP * 16u;

    float ss = 0.f;
    for (int d = d0; d < LD; d += 64, off += OFF_STEP) {
        float v = 0.f;
        if (valid && d < D_REAL) {
            int py = rem / 3, px = rem - py * 3;
            int row = row0 + py, col = col0 + px;
            if (c < 256) {
                v = resp[((uint32_t)c << 16) + ((uint32_t)row << 8) + (uint32_t)col];
            } else {
                int m = c - 256;
                const float* mp = map + (size_t)m * 1024 * 1024 + (size_t)(row * 4) * 1024 + col * 4;
                float s = 0.f;
                #pragma unroll
                for (int u = 0; u < 4; u++)
                    #pragma unroll
                    for (int w = 0; w < 4; w++) s += mp[u * 1024 + w];
                v = s * (50.0f / 16.0f);
            }
        }
        hiDst[off] = __float2half_rn(v);
        ss += v * v;
        c += 7; rem += 1;
        if (rem >= 9) { rem -= 9; c += 1; }
    }
    #pragma unroll
    for (int o = 4; o < 32; o <<= 1) ss += __shfl_xor_sync(0xffffffffu, ss, o);
    int lane = t & 31, w = t >> 5;
    if (lane < 4) red[w][lane] = ss;
    __syncthreads();
    if (t < 32) {
        int pp = t & 3, ww = t >> 2;
        float v2 = red[ww][pp];
        #pragma unroll
        for (int o = 4; o < 32; o <<= 1) v2 += __shfl_xor_sync(0xffffffffu, v2, o);
        if (t < 4) {
            int ii = blockIdx.x * 4 + pp;
            if (isImg) {
                g_in2[ii] = v2;
            } else {
                g_sninv[ii] = (ii < N_REAL) ? rsqrtf(v2) : 0.f;
                g_sn2[ii] = v2;
            }
        }
    }
}

// ---------------- persistent HMMA GEMM, 2 CTA/SM, 128x128 tiles -------------
__device__ __forceinline__ void issue_stage(uint32_t sb, int gst, int bid) {
    int s = gst & 1;
    int tmine = gst / NST;
    int st = gst - tmine * NST;
    int nq = (st == NST - 1) ? LASTQ : CPS;
    int tid = bid + tmine * GRIDC;
    int ty = tid / NTIL_X;
    int i0 = ty * BMr;
    int j0 = (tid - ty * NTIL_X) * BNr;
    uint32_t full = sb + FULL_OFF + s * 8;
    uint32_t stg = sb + TILE_OFF + s * STAGE_B;
    mbar_expect_tx(full, (uint32_t)(nq * CHUNK_B));
    for (int q = 0; q < nq; q++) {
        int cc = st * CPS + q;
        bulkcp(stg + q * CHUNK_B,        g_Ah + ((size_t)cc * NP + i0) * 16, 4096, full);
        bulkcp(stg + q * CHUNK_B + 4096, g_Bh + ((size_t)cc * NP + j0) * 16, 4096, full);
    }
}

struct Frag {
    uint32_t a[2][4];
    uint32_t b[8][2];
};
__device__ __forceinline__ void load_frags(Frag& f, uint32_t cb,
                                           const uint32_t* offA, const uint32_t* offB) {
    #pragma unroll
    for (int mt = 0; mt < 2; mt++) ldsm4(f.a[mt], cb + offA[mt]);
    #pragma unroll
    for (int pt = 0; pt < 4; pt++) {
        uint32_t r[4];
        ldsm4(r, cb + 4096 + offB[pt]);
        f.b[2 * pt][0] = r[0]; f.b[2 * pt][1] = r[1];
        f.b[2 * pt + 1][0] = r[2]; f.b[2 * pt + 1][1] = r[3];
    }
}

template <int NQ>
__device__ __forceinline__ void process_stage(
    uint32_t sb, int& gst, int totalStages, int bid,
    int* phase, const uint32_t* offA, const uint32_t* offB,
    float (*acc)[8][4], int t)
{
    int s = gst & 1;
    uint32_t stg = sb + TILE_OFF + s * STAGE_B;
    mbar_wait(sb + FULL_OFF + s * 8, phase[s]);
    phase[s] ^= 1;
    #pragma unroll
    for (int q = 0; q < NQ; q++) {
        Frag f;
        load_frags(f, stg + q * CHUNK_B, offA, offB);
        #pragma unroll
        for (int mt = 0; mt < 2; mt++)
            #pragma unroll
            for (int nt = 0; nt < 8; nt++)
                mma16816(acc[mt][nt], f.a[mt], f.b[nt]);
    }
    __syncthreads();   // all warps done reading slot s
    if (t == 0 && gst + 2 < totalStages) {
        FENCE_PROXY();
        issue_stage(sb, gst + 2, bid);
    }
    gst++;
}

__global__ void __launch_bounds__(256, 2)
gemm_hmma_persistent() {
    extern __shared__ char smem[];
    uint32_t sb = smem_u32(smem);
    int t = threadIdx.x, lane = t & 31, w = t >> 5;
    int bid = blockIdx.x;
    int nMine = (NTIL - bid + GRIDC - 1) / GRIDC;
    if (nMine <= 0) return;
    int totalStages = nMine * NST;

    if (t < 2) mbar_init(sb + FULL_OFF + t * 8, 1);
    __syncthreads();
    if (t == 0) {
        FENCE_PROXY();
        issue_stage(sb, 0, bid);
        issue_stage(sb, 1, bid);
    }

    int m0 = (w >> 1) * 32;   // warp row offset (0/32/64/96)
    int n0 = (w & 1) * 64;    // warp col offset (0/64)

    uint32_t offA[2], offB[4];
    #pragma unroll
    for (int mt = 0; mt < 2; mt++) {
        int row = m0 + mt * 16 + (lane & 15);
        int seg = lane >> 4;
        offA[mt] = (uint32_t)(row * 32 + ((seg ^ ((row >> 2) & 1)) << 4));
    }
    #pragma unroll
    for (int pt = 0; pt < 4; pt++) {
        int rr = n0 + pt * 16 + ((lane >> 4) << 3) + (lane & 7);
        int seg = (lane >> 3) & 1;
        offB[pt] = (uint32_t)(rr * 32 + ((seg ^ ((rr >> 2) & 1)) << 4));
    }

    float acc[2][8][4];
    #pragma unroll
    for (int a = 0; a < 2; a++)
        #pragma unroll
        for (int b = 0; b < 8; b++)
            #pragma unroll
            for (int q = 0; q < 4; q++) acc[a][b][q] = 0.f;

    int phase[2] = {0, 0};
    int gst = 0;
    for (int tt = 0; tt < nMine; tt++) {
        int tid = bid + tt * GRIDC;
        int ty = tid / NTIL_X;
        int i0 = ty * BMr;
        int j0 = (tid - ty * NTIL_X) * BNr;

        #pragma unroll 1
        for (int st = 0; st < NST - 1; st++)
            process_stage<CPS>(sb, gst, totalStages, bid, phase, offA, offB, acc, t);
        process_stage<LASTQ>(sb, gst, totalStages, bid, phase, offA, offB, acc, t);

        // ---- tile epilogue: scale by sninv[j], per-row argmax, atomicMax ----
        int qlane = lane & 3;
        #pragma unroll
        for (int mt = 0; mt < 2; mt++) {
            #pragma unroll
            for (int h = 0; h < 2; h++) {
                unsigned long long key = 0ull;
                #pragma unroll
                for (int nt = 0; nt < 8; nt++) {
                    #pragma unroll
                    for (int e = 0; e < 2; e++) {
                        int jc = n0 + nt * 8 + 2 * qlane + e;
                        int j = j0 + jc;
                        float v = acc[mt][nt][2 * h + e] * __ldg(&g_sninv[j]);
                        if (j < N_REAL) {
                            unsigned long long k =
                                ((unsigned long long)encf(v) << 32) |
                                (unsigned long long)(0xFFFFFFFFu - (unsigned)j);
                            if (k > key) key = k;
                        }
                    }
                }
                #pragma unroll
                for (int o = 1; o < 4; o <<= 1) {
                    unsigned long long other = __shfl_xor_sync(0xffffffffu, key, o);
                    if (other > key) key = other;
                }
                int m = i0 + m0 + mt * 16 + h * 8 + (lane >> 2);
                if (qlane == 0 && m < N_REAL) atomicMax(&g_best[m], key);
                #pragma unroll
                for (int nt = 0; nt < 8; nt++) {
                    acc[mt][nt][2 * h + 0] = 0.f;
                    acc[mt][nt][2 * h + 1] = 0.f;
                }
            }
        }
    }
}

// ---------------- loss: gather dot + exact norms, last block finalizes ------
__global__ void loss_kernel(float* out) {
    int i = blockIdx.x;
    unsigned long long key = g_best[i];
    unsigned int n = 0xFFFFFFFFu - (unsigned int)(key & 0xFFFFFFFFull);
    int pi = (i >> 2) & 1, pn = ((int)n >> 2) & 1;
    float dot = 0.f;
    for (int g = threadIdx.x; g < LD / 8; g += blockDim.x) {
        int c = g >> 1, seg = g & 1;
        const __half2* ih = (const __half2*)(g_Bh + ((size_t)c * NP + i) * 16 +
                                             (size_t)((seg ^ pi) << 3));
        const __half2* sh2 = (const __half2*)(g_Ah + ((size_t)c * NP + n) * 16 +
                                              (size_t)((seg ^ pn) << 3));
        #pragma unroll
        for (int q = 0; q < 4; q++) {
            float2 a = __half22float2(ih[q]);
            float2 b = __half22float2(sh2[q]);
            dot += a.x * b.x + a.y * b.y;
        }
    }
    dot = block_reduce_sum(dot);
    if (threadIdx.x == 0) {
        float s = g_in2[i] + g_sn2[n] - 2.f * dot;
        atomicAdd(&g_acc, (double)s);
        __threadfence();
        int ticket = atomicAdd(&g_done, 1);
        if (ticket == N_REAL - 1)
            out[0] = (float)(g_acc / ((double)D_REAL * (double)N_REAL));
    }
}

// ---------------- launch ----------------------------------------------------
extern "C" void kernel_launch(void* const* d_in, const int* in_sizes, int n_in,
                              void* d_out, int out_size) {
    const float* bigs[2] = {nullptr, nullptr};
    const float* smalls[2] = {nullptr, nullptr};
    int bi = 0, si = 0;
    for (int k = 0; k < n_in; k++) {
        if (in_sizes[k] == 256 * 256 * 256) { if (bi < 2) bigs[bi++] = (const float*)d_in[k]; }
        else                                { if (si < 2) smalls[si++] = (const float*)d_in[k]; }
    }
    const float* style_resp = bigs[0];
    const float* model_resp = bigs[1];
    const float* style_map  = smalls[0];
    const float* output_map = smalls[1];

    cudaFuncSetAttribute(gemm_hmma_persistent,
                         cudaFuncAttributeMaxDynamicSharedMemorySize, SMEM_TOTAL);

    pack_all<<<dim3(NP / 4, 2), 256>>>(style_resp, style_map, model_resp, output_map);
    gemm_hmma_persistent<<<GRIDC, 256, SMEM_TOTAL>>>();
    loss_kernel<<<N_REAL, 256>>>((float*)d_out);
}